// round 16
// baseline (speedup 1.0000x reference)
#include <cuda_runtime.h>
#include <cuda_bf16.h>
#include <cuda_fp16.h>
#include <cstdint>

// Problem constants
#define Bn   256
#define Nn   197
#define Cc   768
#define Hh   12
#define Dd   64
#define GRID3 14
#define Mtot (Bn * Nn)          // 50432 = 197 * 256
#define BH   (Bn * Hh)          // 3072
#define NPAD 256

// ---------------------------------------------------------------------------
// Scratch
// ---------------------------------------------------------------------------
__device__ __align__(128) __half g_x16[(size_t)Mtot * Cc];   // x fp16, then att+conv (proj A)
__device__ __align__(128) __half g_w1f[(size_t)3 * Cc * Cc]; // Wqkv^T fp16
__device__ __align__(128) __half g_w2f[(size_t)Cc * Cc];     // Wproj^T fp16
__device__ __align__(128) __half g_Q16[(size_t)BH * NPAD * Dd];
__device__ __align__(128) __half g_K16[(size_t)BH * NPAD * Dd];
__device__ __align__(128) __half g_V16[(size_t)BH * NPAD * Dd];

// ---------------------------------------------------------------------------
// Helpers
// ---------------------------------------------------------------------------
__device__ __forceinline__ uint32_t smem_u32(const void* p) {
    uint32_t a;
    asm("{ .reg .u64 t; cvta.to.shared.u64 t, %1; cvt.u32.u64 %0, t; }" : "=r"(a) : "l"(p));
    return a;
}
__device__ __forceinline__ void cp16(uint32_t dst, const void* src) {
    asm volatile("cp.async.cg.shared.global [%0], [%1], 16;" :: "r"(dst), "l"(src));
}
__device__ __forceinline__ void ldsm4(uint32_t* r, uint32_t a) {
    asm volatile("ldmatrix.sync.aligned.m8n8.x4.shared.b16 {%0,%1,%2,%3}, [%4];"
        : "=r"(r[0]), "=r"(r[1]), "=r"(r[2]), "=r"(r[3]) : "r"(a));
}
__device__ __forceinline__ void ldsm2(uint32_t* r, uint32_t a) {
    asm volatile("ldmatrix.sync.aligned.m8n8.x2.shared.b16 {%0,%1}, [%2];"
        : "=r"(r[0]), "=r"(r[1]) : "r"(a));
}
__device__ __forceinline__ void ldsm2t(uint32_t* r, uint32_t a) {
    asm volatile("ldmatrix.sync.aligned.m8n8.x2.trans.shared.b16 {%0,%1}, [%2];"
        : "=r"(r[0]), "=r"(r[1]) : "r"(a));
}
__device__ __forceinline__ void mma16816h(float* c, const uint32_t* a, const uint32_t* b) {
    asm volatile(
        "mma.sync.aligned.m16n8k16.row.col.f32.f16.f16.f32 "
        "{%0,%1,%2,%3}, {%4,%5,%6,%7}, {%8,%9}, {%0,%1,%2,%3};"
        : "+f"(c[0]), "+f"(c[1]), "+f"(c[2]), "+f"(c[3])
        : "r"(a[0]), "r"(a[1]), "r"(a[2]), "r"(a[3]), "r"(b[0]), "r"(b[1]));
}
__device__ __forceinline__ uint32_t pack_h2(float x, float y) {
    __half2 h(__float2half(x), __float2half(y));
    return *reinterpret_cast<uint32_t*>(&h);
}

// ---------------------------------------------------------------------------
// Conversion kernels
// ---------------------------------------------------------------------------
__global__ __launch_bounds__(256) void split16(
    const float* __restrict__ in, __half* __restrict__ out, size_t n4)
{
    size_t i = (size_t)blockIdx.x * 256 + threadIdx.x;
    size_t stride = (size_t)gridDim.x * 256;
    for (; i < n4; i += stride) {
        float4 v = ((const float4*)in)[i];
        ((uint32_t*)out)[i * 2 + 0] = pack_h2(v.x, v.y);
        ((uint32_t*)out)[i * 2 + 1] = pack_h2(v.z, v.w);
    }
}

// W (K x N) row-major -> W^T fp16 [N x K]
__global__ __launch_bounds__(256) void transpose_half(
    const float* __restrict__ W, __half* __restrict__ out, int K, int N)
{
    __shared__ float t[32][33];
    int bx = blockIdx.x * 32, by = blockIdx.y * 32;
    int tx = threadIdx.x, ty = threadIdx.y;
#pragma unroll
    for (int r = 0; r < 32; r += 8)
        t[ty + r][tx] = W[(size_t)(by + ty + r) * N + bx + tx];
    __syncthreads();
#pragma unroll
    for (int r = 0; r < 32; r += 8)
        out[(size_t)(bx + ty + r) * K + by + tx] = __float2half(t[tx][ty + r]);
}

__global__ __launch_bounds__(256) void zero_vpad(__half* __restrict__ V16)
{
    size_t idx = (size_t)blockIdx.x * 256 + threadIdx.x;
    const size_t total = (size_t)BH * (NPAD - Nn) * Dd / 2;
    if (idx >= total) return;
    int d2 = (int)(idx % (Dd / 2));
    size_t t = idx / (Dd / 2);
    int r = Nn + (int)(t % (NPAD - Nn));
    int bh = (int)(t / (NPAD - Nn));
    size_t o = ((size_t)bh * NPAD + r) * Dd + d2 * 2;
    *(uint32_t*)(V16 + o) = 0u;
}

// ---------------------------------------------------------------------------
// fp16 single-pass GEMM: C = A[M,768]*B[N,768]^T + bias
// CTA tile 256x128, 8 warps of 64x64, KC=64, SW128 on 128B rows, 4 stages
// (192KB smem, 1 CTA/SM, ~190 regs). MODE 0: fp32 C. MODE 1: fp16 Q/K/V.
// ---------------------------------------------------------------------------
#define KCH  64
#define NCHH (Cc / KCH)              // 12
#define ATILE 32768                  // 256 rows x 128B
#define BTILE 16384                  // 128 rows x 128B
#define HSTG  (ATILE + BTILE)        // 49152
#define SMEM_GH (4 * HSTG)           // 196608

template<int MODE>
__global__ __launch_bounds__(256, 1)
void tc_gemm_h(const __half* __restrict__ A16, const __half* __restrict__ B16,
               const float* __restrict__ bias, float* __restrict__ C, int N,
               __half* Q16, __half* K16, __half* V16)
{
    extern __shared__ char smem[];
    const uint32_t sb = smem_u32(smem);
    const int tid = threadIdx.x, lane = tid & 31, wid = tid >> 5;
    const int m0 = blockIdx.y * 256, n0 = blockIdx.x * 128;
    const int wm = wid >> 1, wn = wid & 1;   // warp tile 64x64

    // A load: 1 row per thread, 128B (8 cp16). B load: 2 threads/row, 64B each.
    const int arow = tid;
    const uint32_t amk = (uint32_t)(arow & 7) << 4;
    const int brow = tid >> 1, blh = tid & 1;
    const uint32_t bmk = (uint32_t)(brow & 7) << 4;
    const __half* gA = A16 + (size_t)(m0 + arow) * Cc;
    const __half* gB = B16 + (size_t)(n0 + brow) * Cc + blh * 32;

    uint32_t aSw[8], bSw[4];
#pragma unroll
    for (int q = 0; q < 8; ++q)
        aSw[q] = (uint32_t)arow * 128 + (((uint32_t)q * 16) ^ amk);
#pragma unroll
    for (int q = 0; q < 4; ++q)
        bSw[q] = (uint32_t)brow * 128 + (((uint32_t)blh * 64 + q * 16) ^ bmk);

#define LOADH(c, s) do {                                                \
    uint32_t _a = sb + (uint32_t)(s) * HSTG;                            \
    uint32_t _bb = _a + ATILE;                                          \
    int _k = (c) * KCH;                                                 \
    _Pragma("unroll")                                                   \
    for (int q = 0; q < 8; ++q) cp16(_a + aSw[q], gA + _k + q * 8);     \
    _Pragma("unroll")                                                   \
    for (int q = 0; q < 4; ++q) cp16(_bb + bSw[q], gB + _k + q * 8);    \
    asm volatile("cp.async.commit_group;" ::: "memory");                \
} while (0)

    float acc[4][8][4];
#pragma unroll
    for (int i = 0; i < 4; i++)
#pragma unroll
        for (int j = 0; j < 8; j++)
#pragma unroll
            for (int k = 0; k < 4; k++) acc[i][j][k] = 0.f;

    LOADH(0, 0);
    LOADH(1, 1);
    LOADH(2, 2);

    // fragment addressing
    uint32_t aRow[4], aM[4], bRow[4], bM[4];
#pragma unroll
    for (int im = 0; im < 4; ++im) {
        int r = wm * 64 + im * 16 + (lane & 15);
        aRow[im] = (uint32_t)r * 128;
        aM[im] = (uint32_t)(r & 7) << 4;
    }
#pragma unroll
    for (int p = 0; p < 4; ++p) {
        int r = wn * 64 + (p * 2 + (lane >> 4)) * 8 + (lane & 7);
        bRow[p] = (uint32_t)r * 128;
        bM[p] = (uint32_t)(r & 7) << 4;
    }
    const uint32_t acb = ((uint32_t)(lane >> 4)) * 16;
    const uint32_t bcb = ((uint32_t)((lane >> 3) & 1)) * 16;

    for (int c = 0; c < NCHH; ++c) {
        if (c + 2 < NCHH) asm volatile("cp.async.wait_group 2;" ::: "memory");
        else if (c + 1 < NCHH) asm volatile("cp.async.wait_group 1;" ::: "memory");
        else asm volatile("cp.async.wait_group 0;" ::: "memory");
        __syncthreads();

        if (c + 3 < NCHH) LOADH(c + 3, (c + 3) & 3);

        const uint32_t S = sb + (uint32_t)(c & 3) * HSTG;
#pragma unroll
        for (int ks = 0; ks < 4; ++ks) {
            const uint32_t kb = (uint32_t)ks * 32;
            uint32_t bh[8][2];
#pragma unroll
            for (int p = 0; p < 4; ++p) {
                uint32_t a = S + ATILE + bRow[p] + ((bcb + kb) ^ bM[p]);
                uint32_t r4[4];
                ldsm4(r4, a);
                bh[2 * p][0] = r4[0]; bh[2 * p][1] = r4[1];
                bh[2 * p + 1][0] = r4[2]; bh[2 * p + 1][1] = r4[3];
            }
#pragma unroll
            for (int im = 0; im < 4; ++im) {
                uint32_t ah[4];
                ldsm4(ah, S + aRow[im] + ((acb + kb) ^ aM[im]));
#pragma unroll
                for (int jn = 0; jn < 8; ++jn) mma16816h(acc[im][jn], ah, bh[jn]);
            }
        }
    }

    const int g = lane >> 2, tc = (lane & 3) * 2;
    if (MODE == 0) {
#pragma unroll
        for (int im = 0; im < 4; ++im) {
            int row = m0 + wm * 64 + im * 16 + g;
#pragma unroll
            for (int jn = 0; jn < 8; ++jn) {
                int col = n0 + wn * 64 + jn * 8 + tc;
                float b0 = bias[col], b1 = bias[col + 1];
                float2 v0 = make_float2(acc[im][jn][0] + b0, acc[im][jn][1] + b1);
                float2 v1 = make_float2(acc[im][jn][2] + b0, acc[im][jn][3] + b1);
                *(float2*)(C + (size_t)row * N + col)       = v0;
                *(float2*)(C + (size_t)(row + 8) * N + col) = v1;
            }
        }
    } else {
#pragma unroll
        for (int jn = 0; jn < 8; ++jn) {
            int col = n0 + wn * 64 + jn * 8 + tc;
            int t = col / Cc, rem = col - t * Cc;
            int hh = rem >> 6, dd = rem & 63;
            __half* P = (t == 0) ? Q16 : (t == 1) ? K16 : V16;
            float b0 = bias[col], b1 = bias[col + 1];
#pragma unroll
            for (int im = 0; im < 4; ++im) {
                int row0 = m0 + wm * 64 + im * 16 + g;
#pragma unroll
                for (int rr = 0; rr < 2; ++rr) {
                    int row = row0 + rr * 8;
                    int bb = row / Nn, nn = row - bb * Nn;
                    size_t o = (((size_t)bb * Hh + hh) * NPAD + nn) * Dd + dd;
                    *(uint32_t*)(P + o) = pack_h2(acc[im][jn][rr * 2] + b0,
                                                  acc[im][jn][rr * 2 + 1] + b1);
                }
            }
        }
    }
#undef LOADH
}

// ---------------------------------------------------------------------------
// Flash attention, fp16 single-pass (R14): 256 thr, 128 Q rows/CTA, 2 CTAs/SM,
// peeled 16-key tail. fp32 softmax/accumulators. Output -> fp16 proj-A.
// ---------------------------------------------------------------------------
#define ROWB 144
#define FA_KB   9216
#define FA_QB2  18432
#define FA_STG  (2 * FA_KB)
#define SMEM_FA (FA_QB2 + 2 * FA_STG)  // 55296

__global__ __launch_bounds__(256, 2) void flash_attn(
    const __half* __restrict__ Q16, const __half* __restrict__ K16,
    const __half* __restrict__ V16, __half* __restrict__ x16)
{
    extern __shared__ char smem[];
    const uint32_t sb = smem_u32(smem);
    const int mtp = blockIdx.x, bh = blockIdx.y;
    const int b = bh / Hh, h = bh % Hh;
    const int tid = threadIdx.x, lane = tid & 31, w = tid >> 5;
    const int wh = w >> 2, wr = w & 3;

    const uint32_t SQ = sb;

    {
        int row = tid >> 1, half = tid & 1;
        size_t gq = ((size_t)bh * NPAD + mtp * 128 + row) * Dd + half * 32;
        uint32_t d = SQ + row * ROWB + half * 64;
#pragma unroll
        for (int i = 0; i < 4; ++i) cp16(d + i * 16, Q16 + gq + i * 8);
    }
#define LKV(c, s, nrows) do {                                                \
    int row = tid >> 2, qt = tid & 3;                                        \
    if (row < (nrows)) {                                                     \
        size_t gk = ((size_t)bh * NPAD + (c) * 64 + row) * Dd + qt * 16;     \
        uint32_t d = sb + FA_QB2 + (s) * FA_STG + row * ROWB + qt * 32;      \
        cp16(d,              K16 + gk);                                      \
        cp16(d + 16,         K16 + gk + 8);                                  \
        cp16(d + FA_KB,      V16 + gk);                                      \
        cp16(d + FA_KB + 16, V16 + gk + 8);                                  \
    }                                                                        \
    asm volatile("cp.async.commit_group;" ::: "memory");                     \
} while (0)

    LKV(0, 0, 64);
    LKV(1, 1, 64);

    const uint32_t aoff = (uint32_t)(wh * 64 + wr * 16 + (lane & 15)) * ROWB
                        + ((lane >> 4) << 3) * 2;
    const int lb = lane & 15;
    const uint32_t koff = (uint32_t)(lb & 7) * ROWB + ((lb >> 3) << 3) * 2;
    const uint32_t voff = (uint32_t)(lane & 15) * ROWB;

    float oA[8][4];
#pragma unroll
    for (int i = 0; i < 8; i++)
#pragma unroll
        for (int j = 0; j < 4; j++) oA[i][j] = 0.f;
    float mx[2] = {-1e30f, -1e30f}, sum[2] = {0.f, 0.f};
    const int tc = (lane & 3) * 2;
    float sA[8][4];

#define FA_QK(SK, NT)                                                          \
    _Pragma("unroll")                                                          \
    for (int i = 0; i < 8; i++)                                                \
        _Pragma("unroll")                                                      \
        for (int j = 0; j < 4; j++) sA[i][j] = 0.f;                            \
    _Pragma("unroll")                                                          \
    for (int kk = 0; kk < 4; ++kk) {                                           \
        uint32_t q4[4], k2[NT][2];                                             \
        ldsm4(q4, SQ + aoff + kk * 32);                                        \
        _Pragma("unroll")                                                      \
        for (int nt = 0; nt < NT; ++nt)                                        \
            ldsm2(k2[nt], (SK) + koff + (uint32_t)(nt * 8) * ROWB + kk * 32);  \
        _Pragma("unroll")                                                      \
        for (int nt = 0; nt < NT; ++nt) mma16816h(sA[nt], q4, k2[nt]);         \
    }

#define FA_SOFTMAX(c)                                                          \
    _Pragma("unroll")                                                          \
    for (int rt = 0; rt < 2; ++rt) {                                           \
        float m = -1e30f;                                                      \
        _Pragma("unroll")                                                      \
        for (int nt = 0; nt < 8; ++nt) {                                       \
            int j = (c) * 64 + nt * 8 + tc;                                    \
            float v0 = (j < Nn)     ? sA[nt][rt * 2]     * 0.125f : -1e30f;    \
            float v1 = (j + 1 < Nn) ? sA[nt][rt * 2 + 1] * 0.125f : -1e30f;    \
            sA[nt][rt * 2] = v0;                                               \
            sA[nt][rt * 2 + 1] = v1;                                           \
            m = fmaxf(m, fmaxf(v0, v1));                                       \
        }                                                                      \
        m = fmaxf(m, __shfl_xor_sync(~0u, m, 1));                              \
        m = fmaxf(m, __shfl_xor_sync(~0u, m, 2));                              \
        float mn = fmaxf(mx[rt], m);                                           \
        float scl = __expf(mx[rt] - mn);                                       \
        mx[rt] = mn;                                                           \
        float ls = 0.f;                                                        \
        _Pragma("unroll")                                                      \
        for (int nt = 0; nt < 8; ++nt) {                                       \
            float p0 = __expf(sA[nt][rt * 2] - mn);                            \
            float p1 = __expf(sA[nt][rt * 2 + 1] - mn);                        \
            sA[nt][rt * 2] = p0;                                               \
            sA[nt][rt * 2 + 1] = p1;                                           \
            ls += p0 + p1;                                                     \
            oA[nt][rt * 2] *= scl;                                             \
            oA[nt][rt * 2 + 1] *= scl;                                         \
        }                                                                      \
        ls += __shfl_xor_sync(~0u, ls, 1);                                     \
        ls += __shfl_xor_sync(~0u, ls, 2);                                     \
        sum[rt] = sum[rt] * scl + ls;                                          \
    }

#define FA_PV(SV, PKK)                                                         \
    _Pragma("unroll")                                                          \
    for (int kk = 0; kk < PKK; ++kk) {                                         \
        uint32_t ph[4], v2[8][2];                                              \
        ph[0] = pack_h2(sA[2 * kk][0],     sA[2 * kk][1]);                     \
        ph[1] = pack_h2(sA[2 * kk][2],     sA[2 * kk][3]);                     \
        ph[2] = pack_h2(sA[2 * kk + 1][0], sA[2 * kk + 1][1]);                 \
        ph[3] = pack_h2(sA[2 * kk + 1][2], sA[2 * kk + 1][3]);                 \
        _Pragma("unroll")                                                      \
        for (int nd = 0; nd < 8; ++nd)                                         \
            ldsm2t(v2[nd], (SV) + voff + (uint32_t)(kk * 16) * ROWB + nd * 16);\
        _Pragma("unroll")                                                      \
        for (int nd = 0; nd < 8; ++nd) mma16816h(oA[nd], ph, v2[nd]);          \
    }

    for (int c = 0; c < 3; ++c) {
        asm volatile("cp.async.wait_group 1;" ::: "memory");
        __syncthreads();

        const uint32_t SK = sb + FA_QB2 + (c & 1) * FA_STG;
        const uint32_t SV = SK + FA_KB;

        FA_QK(SK, 8)
        FA_SOFTMAX(c)
        FA_PV(SV, 4)

        __syncthreads();
        if (c + 2 < 4) LKV(c + 2, c & 1, (c + 2 == 3) ? 16 : 64);
    }
    {
        asm volatile("cp.async.wait_group 0;" ::: "memory");
        __syncthreads();

        const uint32_t SK = sb + FA_QB2 + (3 & 1) * FA_STG;
        const uint32_t SV = SK + FA_KB;

        FA_QK(SK, 2)
#pragma unroll
        for (int i = 2; i < 8; i++)
#pragma unroll
            for (int j = 0; j < 4; j++) sA[i][j] = -1e30f / 0.125f;
        FA_SOFTMAX(3)
        FA_PV(SV, 1)
    }

    const float i0 = 1.f / sum[0], i1 = 1.f / sum[1];
    const int g = lane >> 2;
    const int q0 = mtp * 128 + wh * 64 + wr * 16 + g;
    const int dcol = h * Dd + tc;
#pragma unroll
    for (int rr = 0; rr < 2; ++rr) {
        int q = q0 + rr * 8;
        if (q >= Nn) continue;
        float inv = rr ? i1 : i0;
        size_t o = ((size_t)b * Nn + q) * Cc + dcol;
#pragma unroll
        for (int nd = 0; nd < 8; ++nd)
            *(uint32_t*)(x16 + o + nd * 8) =
                pack_h2(oA[nd][rr * 2] * inv, oA[nd][rr * 2 + 1] * inv);
    }
#undef LKV
#undef FA_QK
#undef FA_SOFTMAX
#undef FA_PV
}

// ---------------------------------------------------------------------------
// Fused depthwise conv + residual into fp16 proj-A buffer, 2 ch/thread
// ---------------------------------------------------------------------------
__global__ __launch_bounds__(256) void conv_add16(
    const __half* __restrict__ V16,
    const float* __restrict__ wgt, const float* __restrict__ bias,
    __half* __restrict__ x16)
{
    size_t idx = (size_t)blockIdx.x * 256 + threadIdx.x;
    const size_t total = (size_t)Bn * (GRID3 * GRID3) * (Cc / 2);
    if (idx >= total) return;

    int c2 = (int)(idx % (Cc / 2));
    int c = c2 * 2;
    size_t t = idx / (Cc / 2);
    int x = (int)(t % GRID3); t /= GRID3;
    int y = (int)(t % GRID3);
    int b = (int)(t / GRID3);

    int hh = c >> 6, dd = c & 63;
    const size_t vb = ((size_t)(b * Hh + hh) * NPAD) * Dd + dd;

    float a0 = bias[c], a1 = bias[c + 1];
#pragma unroll
    for (int dy = -1; dy <= 1; ++dy) {
        int yy = y + dy;
        if (yy < 0 || yy >= GRID3) continue;
#pragma unroll
        for (int dx = -1; dx <= 1; ++dx) {
            int xx = x + dx;
            if (xx < 0 || xx >= GRID3) continue;
            size_t a = vb + (size_t)(1 + yy * GRID3 + xx) * Dd;
            __half2 v = *(const __half2*)(V16 + a);
            int wi = (dy + 1) * 3 + (dx + 1);
            a0 += __half2float(v.x) * wgt[c * 9 + wi];
            a1 += __half2float(v.y) * wgt[(c + 1) * 9 + wi];
        }
    }
    size_t o = ((size_t)b * Nn + 1 + y * GRID3 + x) * Cc + c;
    __half2 xv = *(__half2*)(x16 + o);
    *(uint32_t*)(x16 + o) = pack_h2(__half2float(xv.x) + a0,
                                    __half2float(xv.y) + a1);
}

// ---------------------------------------------------------------------------
extern "C" void kernel_launch(void* const* d_in, const int* in_sizes, int n_in,
                              void* d_out, int out_size)
{
    (void)in_sizes; (void)n_in; (void)out_size;
    const float* x     = (const float*)d_in[0];
    const float* Wqkv  = (const float*)d_in[1];
    const float* bqkv  = (const float*)d_in[2];
    const float* Wproj = (const float*)d_in[3];
    const float* bproj = (const float*)d_in[4];
    const float* dwcw  = (const float*)d_in[5];
    const float* dwcb  = (const float*)d_in[6];
    float* out = (float*)d_out;

    __half *x16, *w1f, *w2f, *Q16, *K16, *V16;
    cudaGetSymbolAddress((void**)&x16, g_x16);
    cudaGetSymbolAddress((void**)&w1f, g_w1f);
    cudaGetSymbolAddress((void**)&w2f, g_w2f);
    cudaGetSymbolAddress((void**)&Q16, g_Q16);
    cudaGetSymbolAddress((void**)&K16, g_K16);
    cudaGetSymbolAddress((void**)&V16, g_V16);

    cudaFuncSetAttribute(tc_gemm_h<0>, cudaFuncAttributeMaxDynamicSharedMemorySize, SMEM_GH);
    cudaFuncSetAttribute(tc_gemm_h<1>, cudaFuncAttributeMaxDynamicSharedMemorySize, SMEM_GH);
    cudaFuncSetAttribute(flash_attn, cudaFuncAttributeMaxDynamicSharedMemorySize, SMEM_FA);

    const size_t nX4 = (size_t)Mtot * Cc / 4;

    // 1) x -> fp16 ; Wqkv^T, Wproj^T -> fp16 ; zero V padding
    split16<<<2048, 256>>>(x, x16, nX4);
    {
        dim3 g(3 * Cc / 32, Cc / 32), blk(32, 8);
        transpose_half<<<g, blk>>>(Wqkv, w1f, Cc, 3 * Cc);
    }
    {
        dim3 g(Cc / 32, Cc / 32), blk(32, 8);
        transpose_half<<<g, blk>>>(Wproj, w2f, Cc, Cc);
    }
    {
        size_t tot = (size_t)BH * (NPAD - Nn) * Dd / 2;
        zero_vpad<<<(int)((tot + 255) / 256), 256>>>(V16);
    }
    // 2) qkv GEMM (fp16, 256x128 tiles) -> padded Q/K/V fp16
    {
        dim3 grid(3 * Cc / 128, Mtot / 256);
        tc_gemm_h<1><<<grid, 256, SMEM_GH>>>(x16, w1f, bqkv, nullptr, 3 * Cc,
                                             Q16, K16, V16);
    }
    // 3) flash attention (fp16) -> x16
    {
        dim3 grid(2, BH);
        flash_attn<<<grid, 256, SMEM_FA>>>(Q16, K16, V16, x16);
    }
    // 4) depthwise conv + residual into x16
    {
        size_t total = (size_t)Bn * (GRID3 * GRID3) * (Cc / 2);
        conv_add16<<<(int)((total + 255) / 256), 256>>>(V16, dwcw, dwcb, x16);
    }
    // 5) proj GEMM (fp16, 256x128 tiles) -> out
    {
        dim3 grid(Cc / 128, Mtot / 256);
        tc_gemm_h<0><<<grid, 256, SMEM_GH>>>(x16, w2f, bproj, out, Cc,
                                             nullptr, nullptr, nullptr);
    }
}

// round 17
// speedup vs baseline: 1.1324x; 1.1324x over previous
#include <cuda_runtime.h>
#include <cuda_bf16.h>
#include <cuda_fp16.h>
#include <cstdint>

// Problem constants
#define Bn   256
#define Nn   197
#define Cc   768
#define Hh   12
#define Dd   64
#define GRID3 14
#define Mtot (Bn * Nn)          // 50432 = 394 * 128
#define BH   (Bn * Hh)          // 3072
#define NPAD 256
#define VPAD_ROWS 11            // flash reads V rows < 208 only

// ---------------------------------------------------------------------------
// Scratch
// ---------------------------------------------------------------------------
__device__ __align__(128) __half g_x16[(size_t)Mtot * Cc];   // x fp16, then att+conv (proj A)
__device__ __align__(128) __half g_w1f[(size_t)3 * Cc * Cc]; // Wqkv^T fp16
__device__ __align__(128) __half g_w2f[(size_t)Cc * Cc];     // Wproj^T fp16
__device__ __align__(128) __half g_Q16[(size_t)BH * NPAD * Dd];
__device__ __align__(128) __half g_K16[(size_t)BH * NPAD * Dd];
__device__ __align__(128) __half g_V16[(size_t)BH * NPAD * Dd];

// ---------------------------------------------------------------------------
// Helpers
// ---------------------------------------------------------------------------
__device__ __forceinline__ uint32_t smem_u32(const void* p) {
    uint32_t a;
    asm("{ .reg .u64 t; cvta.to.shared.u64 t, %1; cvt.u32.u64 %0, t; }" : "=r"(a) : "l"(p));
    return a;
}
__device__ __forceinline__ void cp16(uint32_t dst, const void* src) {
    asm volatile("cp.async.cg.shared.global [%0], [%1], 16;" :: "r"(dst), "l"(src));
}
__device__ __forceinline__ void ldsm4(uint32_t* r, uint32_t a) {
    asm volatile("ldmatrix.sync.aligned.m8n8.x4.shared.b16 {%0,%1,%2,%3}, [%4];"
        : "=r"(r[0]), "=r"(r[1]), "=r"(r[2]), "=r"(r[3]) : "r"(a));
}
__device__ __forceinline__ void ldsm2(uint32_t* r, uint32_t a) {
    asm volatile("ldmatrix.sync.aligned.m8n8.x2.shared.b16 {%0,%1}, [%2];"
        : "=r"(r[0]), "=r"(r[1]) : "r"(a));
}
__device__ __forceinline__ void ldsm2t(uint32_t* r, uint32_t a) {
    asm volatile("ldmatrix.sync.aligned.m8n8.x2.trans.shared.b16 {%0,%1}, [%2];"
        : "=r"(r[0]), "=r"(r[1]) : "r"(a));
}
__device__ __forceinline__ void mma16816h(float* c, const uint32_t* a, const uint32_t* b) {
    asm volatile(
        "mma.sync.aligned.m16n8k16.row.col.f32.f16.f16.f32 "
        "{%0,%1,%2,%3}, {%4,%5,%6,%7}, {%8,%9}, {%0,%1,%2,%3};"
        : "+f"(c[0]), "+f"(c[1]), "+f"(c[2]), "+f"(c[3])
        : "r"(a[0]), "r"(a[1]), "r"(a[2]), "r"(a[3]), "r"(b[0]), "r"(b[1]));
}
__device__ __forceinline__ uint32_t pack_h2(float x, float y) {
    __half2 h(__float2half(x), __float2half(y));
    return *reinterpret_cast<uint32_t*>(&h);
}

// ---------------------------------------------------------------------------
// Conversion kernels
// ---------------------------------------------------------------------------
__global__ __launch_bounds__(256) void split16(
    const float* __restrict__ in, __half* __restrict__ out, size_t n4)
{
    size_t i = (size_t)blockIdx.x * 256 + threadIdx.x;
    size_t stride = (size_t)gridDim.x * 256;
    for (; i < n4; i += stride) {
        float4 v = ((const float4*)in)[i];
        ((uint32_t*)out)[i * 2 + 0] = pack_h2(v.x, v.y);
        ((uint32_t*)out)[i * 2 + 1] = pack_h2(v.z, v.w);
    }
}

// W (K x N) row-major -> W^T fp16 [N x K]
__global__ __launch_bounds__(256) void transpose_half(
    const float* __restrict__ W, __half* __restrict__ out, int K, int N)
{
    __shared__ float t[32][33];
    int bx = blockIdx.x * 32, by = blockIdx.y * 32;
    int tx = threadIdx.x, ty = threadIdx.y;
#pragma unroll
    for (int r = 0; r < 32; r += 8)
        t[ty + r][tx] = W[(size_t)(by + ty + r) * N + bx + tx];
    __syncthreads();
#pragma unroll
    for (int r = 0; r < 32; r += 8)
        out[(size_t)(bx + ty + r) * K + by + tx] = __float2half(t[tx][ty + r]);
}

// zero V rows 197..207 only (flash tail reads rows < 208)
__global__ __launch_bounds__(256) void zero_vpad(__half* __restrict__ V16)
{
    size_t idx = (size_t)blockIdx.x * 256 + threadIdx.x;
    const size_t total = (size_t)BH * VPAD_ROWS * Dd / 2;
    if (idx >= total) return;
    int d2 = (int)(idx % (Dd / 2));
    size_t t = idx / (Dd / 2);
    int r = Nn + (int)(t % VPAD_ROWS);
    int bh = (int)(t / VPAD_ROWS);
    size_t o = ((size_t)bh * NPAD + r) * Dd + d2 * 2;
    *(uint32_t*)(V16 + o) = 0u;
}

// ---------------------------------------------------------------------------
// fp16 single-pass GEMM (R14 config): 128x128 CTA tile, 8 warps 64x32, KC=64,
// SW128 on 128B rows, 3 stages, 2 CTAs/SM. MODE 0: fp32 C. MODE 1: fp16 Q/K/V.
// ---------------------------------------------------------------------------
#define KCH  64
#define NCHH (Cc / KCH)              // 12
#define HTILE 16384                  // 128 rows x 128B
#define HSTG  (2 * HTILE)            // 32768
#define SMEM_GH (3 * HSTG)           // 98304

template<int MODE>
__global__ __launch_bounds__(256, 2)
void tc_gemm_h(const __half* __restrict__ A16, const __half* __restrict__ B16,
               const float* __restrict__ bias, float* __restrict__ C, int N,
               __half* Q16, __half* K16, __half* V16)
{
    extern __shared__ char smem[];
    const uint32_t sb = smem_u32(smem);
    const int tid = threadIdx.x, lane = tid & 31, wid = tid >> 5;
    const int m0 = blockIdx.y * 128, n0 = blockIdx.x * 128;
    const int wm = wid >> 2, wn = wid & 3;

    const int lrow = tid >> 1;
    const int lh   = tid & 1;
    const uint32_t mrow = (uint32_t)(lrow & 7) << 4;
    uint32_t sw[4];
#pragma unroll
    for (int q = 0; q < 4; ++q)
        sw[q] = (uint32_t)lrow * 128 + (((uint32_t)lh * 64 + q * 16) ^ mrow);
    const __half* gA = A16 + (size_t)(m0 + lrow) * Cc + lh * 32;
    const __half* gB = B16 + (size_t)(n0 + lrow) * Cc + lh * 32;

#define LOADH(c, s) do {                                                \
    uint32_t _b = sb + (uint32_t)(s) * HSTG;                            \
    int _k = (c) * KCH;                                                 \
    _Pragma("unroll")                                                   \
    for (int q = 0; q < 4; ++q) {                                       \
        cp16(_b + sw[q],         gA + _k + q * 8);                      \
        cp16(_b + HTILE + sw[q], gB + _k + q * 8);                      \
    }                                                                   \
    asm volatile("cp.async.commit_group;" ::: "memory");                \
} while (0)

    float acc[4][4][4];
#pragma unroll
    for (int i = 0; i < 4; i++)
#pragma unroll
        for (int j = 0; j < 4; j++)
#pragma unroll
            for (int k = 0; k < 4; k++) acc[i][j][k] = 0.f;

    LOADH(0, 0);
    LOADH(1, 1);

    uint32_t aRow[4], aM[4], bRow[2], bM[2];
#pragma unroll
    for (int im = 0; im < 4; ++im) {
        int r = wm * 64 + im * 16 + (lane & 15);
        aRow[im] = (uint32_t)r * 128;
        aM[im] = (uint32_t)(r & 7) << 4;
    }
#pragma unroll
    for (int p = 0; p < 2; ++p) {
        int r = wn * 32 + (p * 2 + (lane >> 4)) * 8 + (lane & 7);
        bRow[p] = (uint32_t)r * 128;
        bM[p] = (uint32_t)(r & 7) << 4;
    }
    const uint32_t acb = ((uint32_t)(lane >> 4)) * 16;
    const uint32_t bcb = ((uint32_t)((lane >> 3) & 1)) * 16;

    for (int c = 0; c < NCHH; ++c) {
        if (c + 1 < NCHH) asm volatile("cp.async.wait_group 1;" ::: "memory");
        else              asm volatile("cp.async.wait_group 0;" ::: "memory");
        __syncthreads();

        if (c + 2 < NCHH) LOADH(c + 2, (c + 2) % 3);

        const uint32_t S = sb + (uint32_t)(c % 3) * HSTG;
#pragma unroll
        for (int ks = 0; ks < 4; ++ks) {
            const uint32_t kb = (uint32_t)ks * 32;
            uint32_t bh[4][2];
#pragma unroll
            for (int p = 0; p < 2; ++p) {
                uint32_t a = S + HTILE + bRow[p] + ((bcb + kb) ^ bM[p]);
                uint32_t r4[4];
                ldsm4(r4, a);
                bh[2 * p][0] = r4[0]; bh[2 * p][1] = r4[1];
                bh[2 * p + 1][0] = r4[2]; bh[2 * p + 1][1] = r4[3];
            }
#pragma unroll
            for (int im = 0; im < 4; ++im) {
                uint32_t ah[4];
                ldsm4(ah, S + aRow[im] + ((acb + kb) ^ aM[im]));
#pragma unroll
                for (int jn = 0; jn < 4; ++jn) mma16816h(acc[im][jn], ah, bh[jn]);
            }
        }
    }

    const int g = lane >> 2, tc = (lane & 3) * 2;
    if (MODE == 0) {
#pragma unroll
        for (int im = 0; im < 4; ++im) {
            int row = m0 + wm * 64 + im * 16 + g;
#pragma unroll
            for (int jn = 0; jn < 4; ++jn) {
                int col = n0 + wn * 32 + jn * 8 + tc;
                float b0 = bias[col], b1 = bias[col + 1];
                float2 v0 = make_float2(acc[im][jn][0] + b0, acc[im][jn][1] + b1);
                float2 v1 = make_float2(acc[im][jn][2] + b0, acc[im][jn][3] + b1);
                *(float2*)(C + (size_t)row * N + col)       = v0;
                *(float2*)(C + (size_t)(row + 8) * N + col) = v1;
            }
        }
    } else {
#pragma unroll
        for (int jn = 0; jn < 4; ++jn) {
            int col = n0 + wn * 32 + jn * 8 + tc;
            int t = col / Cc, rem = col - t * Cc;
            int hh = rem >> 6, dd = rem & 63;
            __half* P = (t == 0) ? Q16 : (t == 1) ? K16 : V16;
            float b0 = bias[col], b1 = bias[col + 1];
#pragma unroll
            for (int im = 0; im < 4; ++im) {
                int row0 = m0 + wm * 64 + im * 16 + g;
#pragma unroll
                for (int rr = 0; rr < 2; ++rr) {
                    int row = row0 + rr * 8;
                    int bb = row / Nn, nn = row - bb * Nn;
                    size_t o = (((size_t)bb * Hh + hh) * NPAD + nn) * Dd + dd;
                    *(uint32_t*)(P + o) = pack_h2(acc[im][jn][rr * 2] + b0,
                                                  acc[im][jn][rr * 2 + 1] + b1);
                }
            }
        }
    }
#undef LOADH
}

// ---------------------------------------------------------------------------
// Flash attention, fp16 single-pass (R14): 256 thr, 128 Q rows/CTA, 2 CTAs/SM,
// peeled 16-key tail. fp32 softmax/accumulators. Output -> fp16 proj-A.
// ---------------------------------------------------------------------------
#define ROWB 144
#define FA_KB   9216
#define FA_QB2  18432
#define FA_STG  (2 * FA_KB)
#define SMEM_FA (FA_QB2 + 2 * FA_STG)  // 55296

__global__ __launch_bounds__(256, 2) void flash_attn(
    const __half* __restrict__ Q16, const __half* __restrict__ K16,
    const __half* __restrict__ V16, __half* __restrict__ x16)
{
    extern __shared__ char smem[];
    const uint32_t sb = smem_u32(smem);
    const int mtp = blockIdx.x, bh = blockIdx.y;
    const int b = bh / Hh, h = bh % Hh;
    const int tid = threadIdx.x, lane = tid & 31, w = tid >> 5;
    const int wh = w >> 2, wr = w & 3;

    const uint32_t SQ = sb;

    {
        int row = tid >> 1, half = tid & 1;
        size_t gq = ((size_t)bh * NPAD + mtp * 128 + row) * Dd + half * 32;
        uint32_t d = SQ + row * ROWB + half * 64;
#pragma unroll
        for (int i = 0; i < 4; ++i) cp16(d + i * 16, Q16 + gq + i * 8);
    }
#define LKV(c, s, nrows) do {                                                \
    int row = tid >> 2, qt = tid & 3;                                        \
    if (row < (nrows)) {                                                     \
        size_t gk = ((size_t)bh * NPAD + (c) * 64 + row) * Dd + qt * 16;     \
        uint32_t d = sb + FA_QB2 + (s) * FA_STG + row * ROWB + qt * 32;      \
        cp16(d,              K16 + gk);                                      \
        cp16(d + 16,         K16 + gk + 8);                                  \
        cp16(d + FA_KB,      V16 + gk);                                      \
        cp16(d + FA_KB + 16, V16 + gk + 8);                                  \
    }                                                                        \
    asm volatile("cp.async.commit_group;" ::: "memory");                     \
} while (0)

    LKV(0, 0, 64);
    LKV(1, 1, 64);

    const uint32_t aoff = (uint32_t)(wh * 64 + wr * 16 + (lane & 15)) * ROWB
                        + ((lane >> 4) << 3) * 2;
    const int lb = lane & 15;
    const uint32_t koff = (uint32_t)(lb & 7) * ROWB + ((lb >> 3) << 3) * 2;
    const uint32_t voff = (uint32_t)(lane & 15) * ROWB;

    float oA[8][4];
#pragma unroll
    for (int i = 0; i < 8; i++)
#pragma unroll
        for (int j = 0; j < 4; j++) oA[i][j] = 0.f;
    float mx[2] = {-1e30f, -1e30f}, sum[2] = {0.f, 0.f};
    const int tc = (lane & 3) * 2;
    float sA[8][4];

#define FA_QK(SK, NT)                                                          \
    _Pragma("unroll")                                                          \
    for (int i = 0; i < 8; i++)                                                \
        _Pragma("unroll")                                                      \
        for (int j = 0; j < 4; j++) sA[i][j] = 0.f;                            \
    _Pragma("unroll")                                                          \
    for (int kk = 0; kk < 4; ++kk) {                                           \
        uint32_t q4[4], k2[NT][2];                                             \
        ldsm4(q4, SQ + aoff + kk * 32);                                        \
        _Pragma("unroll")                                                      \
        for (int nt = 0; nt < NT; ++nt)                                        \
            ldsm2(k2[nt], (SK) + koff + (uint32_t)(nt * 8) * ROWB + kk * 32);  \
        _Pragma("unroll")                                                      \
        for (int nt = 0; nt < NT; ++nt) mma16816h(sA[nt], q4, k2[nt]);         \
    }

#define FA_SOFTMAX(c)                                                          \
    _Pragma("unroll")                                                          \
    for (int rt = 0; rt < 2; ++rt) {                                           \
        float m = -1e30f;                                                      \
        _Pragma("unroll")                                                      \
        for (int nt = 0; nt < 8; ++nt) {                                       \
            int j = (c) * 64 + nt * 8 + tc;                                    \
            float v0 = (j < Nn)     ? sA[nt][rt * 2]     * 0.125f : -1e30f;    \
            float v1 = (j + 1 < Nn) ? sA[nt][rt * 2 + 1] * 0.125f : -1e30f;    \
            sA[nt][rt * 2] = v0;                                               \
            sA[nt][rt * 2 + 1] = v1;                                           \
            m = fmaxf(m, fmaxf(v0, v1));                                       \
        }                                                                      \
        m = fmaxf(m, __shfl_xor_sync(~0u, m, 1));                              \
        m = fmaxf(m, __shfl_xor_sync(~0u, m, 2));                              \
        float mn = fmaxf(mx[rt], m);                                           \
        float scl = __expf(mx[rt] - mn);                                       \
        mx[rt] = mn;                                                           \
        float ls = 0.f;                                                        \
        _Pragma("unroll")                                                      \
        for (int nt = 0; nt < 8; ++nt) {                                       \
            float p0 = __expf(sA[nt][rt * 2] - mn);                            \
            float p1 = __expf(sA[nt][rt * 2 + 1] - mn);                        \
            sA[nt][rt * 2] = p0;                                               \
            sA[nt][rt * 2 + 1] = p1;                                           \
            ls += p0 + p1;                                                     \
            oA[nt][rt * 2] *= scl;                                             \
            oA[nt][rt * 2 + 1] *= scl;                                         \
        }                                                                      \
        ls += __shfl_xor_sync(~0u, ls, 1);                                     \
        ls += __shfl_xor_sync(~0u, ls, 2);                                     \
        sum[rt] = sum[rt] * scl + ls;                                          \
    }

#define FA_PV(SV, PKK)                                                         \
    _Pragma("unroll")                                                          \
    for (int kk = 0; kk < PKK; ++kk) {                                         \
        uint32_t ph[4], v2[8][2];                                              \
        ph[0] = pack_h2(sA[2 * kk][0],     sA[2 * kk][1]);                     \
        ph[1] = pack_h2(sA[2 * kk][2],     sA[2 * kk][3]);                     \
        ph[2] = pack_h2(sA[2 * kk + 1][0], sA[2 * kk + 1][1]);                 \
        ph[3] = pack_h2(sA[2 * kk + 1][2], sA[2 * kk + 1][3]);                 \
        _Pragma("unroll")                                                      \
        for (int nd = 0; nd < 8; ++nd)                                         \
            ldsm2t(v2[nd], (SV) + voff + (uint32_t)(kk * 16) * ROWB + nd * 16);\
        _Pragma("unroll")                                                      \
        for (int nd = 0; nd < 8; ++nd) mma16816h(oA[nd], ph, v2[nd]);          \
    }

    for (int c = 0; c < 3; ++c) {
        asm volatile("cp.async.wait_group 1;" ::: "memory");
        __syncthreads();

        const uint32_t SK = sb + FA_QB2 + (c & 1) * FA_STG;
        const uint32_t SV = SK + FA_KB;

        FA_QK(SK, 8)
        FA_SOFTMAX(c)
        FA_PV(SV, 4)

        __syncthreads();
        if (c + 2 < 4) LKV(c + 2, c & 1, (c + 2 == 3) ? 16 : 64);
    }
    {
        asm volatile("cp.async.wait_group 0;" ::: "memory");
        __syncthreads();

        const uint32_t SK = sb + FA_QB2 + (3 & 1) * FA_STG;
        const uint32_t SV = SK + FA_KB;

        FA_QK(SK, 2)
#pragma unroll
        for (int i = 2; i < 8; i++)
#pragma unroll
            for (int j = 0; j < 4; j++) sA[i][j] = -1e30f / 0.125f;
        FA_SOFTMAX(3)
        FA_PV(SV, 1)
    }

    const float i0 = 1.f / sum[0], i1 = 1.f / sum[1];
    const int g = lane >> 2;
    const int q0 = mtp * 128 + wh * 64 + wr * 16 + g;
    const int dcol = h * Dd + tc;
#pragma unroll
    for (int rr = 0; rr < 2; ++rr) {
        int q = q0 + rr * 8;
        if (q >= Nn) continue;
        float inv = rr ? i1 : i0;
        size_t o = ((size_t)b * Nn + q) * Cc + dcol;
#pragma unroll
        for (int nd = 0; nd < 8; ++nd)
            *(uint32_t*)(x16 + o + nd * 8) =
                pack_h2(oA[nd][rr * 2] * inv, oA[nd][rr * 2 + 1] * inv);
    }
#undef LKV
#undef FA_QK
#undef FA_SOFTMAX
#undef FA_PV
}

// ---------------------------------------------------------------------------
// Fused depthwise conv + residual into fp16 proj-A buffer, 2 ch/thread
// ---------------------------------------------------------------------------
__global__ __launch_bounds__(256) void conv_add16(
    const __half* __restrict__ V16,
    const float* __restrict__ wgt, const float* __restrict__ bias,
    __half* __restrict__ x16)
{
    size_t idx = (size_t)blockIdx.x * 256 + threadIdx.x;
    const size_t total = (size_t)Bn * (GRID3 * GRID3) * (Cc / 2);
    if (idx >= total) return;

    int c2 = (int)(idx % (Cc / 2));
    int c = c2 * 2;
    size_t t = idx / (Cc / 2);
    int x = (int)(t % GRID3); t /= GRID3;
    int y = (int)(t % GRID3);
    int b = (int)(t / GRID3);

    int hh = c >> 6, dd = c & 63;
    const size_t vb = ((size_t)(b * Hh + hh) * NPAD) * Dd + dd;

    float a0 = bias[c], a1 = bias[c + 1];
#pragma unroll
    for (int dy = -1; dy <= 1; ++dy) {
        int yy = y + dy;
        if (yy < 0 || yy >= GRID3) continue;
#pragma unroll
        for (int dx = -1; dx <= 1; ++dx) {
            int xx = x + dx;
            if (xx < 0 || xx >= GRID3) continue;
            size_t a = vb + (size_t)(1 + yy * GRID3 + xx) * Dd;
            __half2 v = *(const __half2*)(V16 + a);
            int wi = (dy + 1) * 3 + (dx + 1);
            a0 += __half2float(v.x) * wgt[c * 9 + wi];
            a1 += __half2float(v.y) * wgt[(c + 1) * 9 + wi];
        }
    }
    size_t o = ((size_t)b * Nn + 1 + y * GRID3 + x) * Cc + c;
    __half2 xv = *(__half2*)(x16 + o);
    *(uint32_t*)(x16 + o) = pack_h2(__half2float(xv.x) + a0,
                                    __half2float(xv.y) + a1);
}

// ---------------------------------------------------------------------------
extern "C" void kernel_launch(void* const* d_in, const int* in_sizes, int n_in,
                              void* d_out, int out_size)
{
    (void)in_sizes; (void)n_in; (void)out_size;
    const float* x     = (const float*)d_in[0];
    const float* Wqkv  = (const float*)d_in[1];
    const float* bqkv  = (const float*)d_in[2];
    const float* Wproj = (const float*)d_in[3];
    const float* bproj = (const float*)d_in[4];
    const float* dwcw  = (const float*)d_in[5];
    const float* dwcb  = (const float*)d_in[6];
    float* out = (float*)d_out;

    __half *x16, *w1f, *w2f, *Q16, *K16, *V16;
    cudaGetSymbolAddress((void**)&x16, g_x16);
    cudaGetSymbolAddress((void**)&w1f, g_w1f);
    cudaGetSymbolAddress((void**)&w2f, g_w2f);
    cudaGetSymbolAddress((void**)&Q16, g_Q16);
    cudaGetSymbolAddress((void**)&K16, g_K16);
    cudaGetSymbolAddress((void**)&V16, g_V16);

    cudaFuncSetAttribute(tc_gemm_h<0>, cudaFuncAttributeMaxDynamicSharedMemorySize, SMEM_GH);
    cudaFuncSetAttribute(tc_gemm_h<1>, cudaFuncAttributeMaxDynamicSharedMemorySize, SMEM_GH);
    cudaFuncSetAttribute(flash_attn, cudaFuncAttributeMaxDynamicSharedMemorySize, SMEM_FA);

    const size_t nX4 = (size_t)Mtot * Cc / 4;

    // 1) x -> fp16 ; Wqkv^T, Wproj^T -> fp16 ; zero V padding rows 197..207
    split16<<<2048, 256>>>(x, x16, nX4);
    {
        dim3 g(3 * Cc / 32, Cc / 32), blk(32, 8);
        transpose_half<<<g, blk>>>(Wqkv, w1f, Cc, 3 * Cc);
    }
    {
        dim3 g(Cc / 32, Cc / 32), blk(32, 8);
        transpose_half<<<g, blk>>>(Wproj, w2f, Cc, Cc);
    }
    {
        size_t tot = (size_t)BH * VPAD_ROWS * Dd / 2;
        zero_vpad<<<(int)((tot + 255) / 256), 256>>>(V16);
    }
    // 2) qkv GEMM (fp16, 128x128 tiles, 2 CTAs/SM) -> padded Q/K/V fp16
    {
        dim3 grid(3 * Cc / 128, Mtot / 128);
        tc_gemm_h<1><<<grid, 256, SMEM_GH>>>(x16, w1f, bqkv, nullptr, 3 * Cc,
                                             Q16, K16, V16);
    }
    // 3) flash attention (fp16) -> x16
    {
        dim3 grid(2, BH);
        flash_attn<<<grid, 256, SMEM_FA>>>(Q16, K16, V16, x16);
    }
    // 4) depthwise conv + residual into x16
    {
        size_t total = (size_t)Bn * (GRID3 * GRID3) * (Cc / 2);
        conv_add16<<<(int)((total + 255) / 256), 256>>>(V16, dwcw, dwcb, x16);
    }
    // 5) proj GEMM (fp16, 128x128 tiles) -> out
    {
        dim3 grid(Cc / 128, Mtot / 128);
        tc_gemm_h<0><<<grid, 256, SMEM_GH>>>(x16, w2f, bproj, out, Cc,
                                             nullptr, nullptr, nullptr);
    }
}